// round 6
// baseline (speedup 1.0000x reference)
#include <cuda_runtime.h>
#include <math.h>

#define HSZ 1024
#define WSZ 1024
#define NIMG 12          // B*C = 4*3
#define TILE 32

typedef unsigned long long ull;

// ---------------------------------------------------------------------------
// Compile-time Gaussian weights (KSIZE=15, SIGMA=3) via constexpr exp-series.
// ---------------------------------------------------------------------------
__host__ __device__ constexpr double cexp_(double x) {
    double t = 1.0, s = 1.0;
    for (int i = 1; i < 60; ++i) { t *= x / i; s += t; }
    return s;
}
__host__ __device__ constexpr double gsum_() {
    double s = 0.0;
    for (int i = 0; i < 15; ++i) { double d = i - 7; s += cexp_(-d * d / 18.0); }
    return s;
}
__host__ __device__ constexpr float gw_(int k) {
    double d = k - 7; return (float)(cexp_(-d * d / 18.0) / gsum_());
}

// ---- packed f32x2 helpers (FFMA2 path: PTX-only, per SASS_PATTERNS) -------
__device__ __forceinline__ ull fma2(ull a, ull b, ull c) {
    ull d; asm("fma.rn.f32x2 %0, %1, %2, %3;" : "=l"(d) : "l"(a), "l"(b), "l"(c));
    return d;
}
__device__ __forceinline__ ull pack2(float lo, float hi) {
    ull d; asm("mov.b64 %0, {%1, %2};" : "=l"(d) : "f"(lo), "f"(hi));
    return d;
}
__device__ __forceinline__ void unpack2(ull v, float& lo, float& hi) {
    asm("mov.b64 {%0, %1}, %2;" : "=f"(lo), "=f"(hi) : "l"(v));
}

// ---------------------------------------------------------------------------
// One fused kernel per 32x32 output tile. All blur phases use explicit
// register windows (static indices only) + packed f32x2 FMAs:
//   phase0: 60x60 halo load + pointwise chain -> sA       (stride 61)
//   H1:  sA -> sB [60 x 46]                               (stride 48, 2-row pairs)
//   V1:  sB -> sC [46 x 46] (+LCE epilogue, zero-padded)  (stride 48, 2-col pairs)
//   H2:  sC -> sD [46 x 32] (sD aliases sA)               (stride 34, 2-row pairs)
//   V2:  sD -> out (+softness + gradient mask)            (2-col pairs)
// ---------------------------------------------------------------------------
__global__ __launch_bounds__(256, 3) void proc_kernel(
    const float* __restrict__ x,
    const float* __restrict__ gains,
    const float* __restrict__ p_gamma,
    const float* __restrict__ p_sb,
    const float* __restrict__ p_hr,
    const float* __restrict__ p_br,
    const float* __restrict__ p_ct,
    const float* __restrict__ p_ea,
    const float* __restrict__ p_soft,
    const float* __restrict__ p_int,
    const float* __restrict__ p_rot,
    const float* __restrict__ p_hard,
    float* __restrict__ out)
{
    constexpr float GW[15] = {gw_(0), gw_(1), gw_(2),  gw_(3),  gw_(4),  gw_(5),  gw_(6), gw_(7),
                              gw_(8), gw_(9), gw_(10), gw_(11), gw_(12), gw_(13), gw_(14)};

    __shared__ __align__(16) float sA[3664];      // 60 x (stride 61) + overrun pad; H2 result aliases this
    __shared__ __align__(16) float sB[62 * 48];   // H1 result: 60 rows valid, 2 junk overrun rows
    __shared__ __align__(16) float sC[46 * 48];   // x5 (zero outside image)
    __shared__ __align__(16) ull   sW[15];        // broadcast weight pairs

    float* const sD = sA;                          // 46 x (stride 34) = 1564 floats < 3664

    const int tid = threadIdx.x;
    const int img = blockIdx.z;
    const int ch  = img % 3;
    const int ty0 = blockIdx.y * TILE;
    const int tx0 = blockIdx.x * TILE;

    const float gain = gains[ch];
    const float gam  = p_gamma[0];
    const float sbv  = p_sb[0],  hrv = p_hr[0];
    const float brv  = p_br[0],  ctv = p_ct[0];
    const float eav  = p_ea[0],  sof = p_soft[0];
    const float itn  = p_int[0], hrd = p_hard[0];
    float snt, cst;
    sincosf(p_rot[0] * 0.017453292519943295f, &snt, &cst);

    const float* __restrict__ xin = x + (size_t)img * (HSZ * WSZ);

    // ---- weight pairs (one thread, static indices) ----
    if (tid == 0) {
        #pragma unroll
        for (int k = 0; k < 15; ++k) sW[k] = pack2(GW[k], GW[k]);
    }

    // ---- Phase 0: halo load + pointwise chain ----
    auto pointwise = [&](float v) -> float {
        v = v * gain;                                         // white balance
        v = __powf(v, gam);                                   // tone curve
        float hi = 1.f / (1.f + __expf((0.5f - v) * 10.f));
        v = v + sbv * (1.f - hi) - hrv * hi;                  // shadow/highlight
        v = fminf(fmaxf(v, 0.f), 1.f);
        v = fmaf(ctv, v - 0.5f, 0.5f + brv);                  // brightness/contrast
        return fminf(fmaxf(v, 0.f), 1.f);
    };

    const bool interior = (ty0 >= 14) && (ty0 + 46 <= HSZ) && (tx0 >= 14) && (tx0 + 46 <= WSZ);
    if (interior) {
        const float* __restrict__ base = xin + (ty0 - 14) * WSZ + (tx0 - 14);
        for (int i = tid; i < 60 * 60; i += 256) {
            int r = i / 60, cc = i - r * 60;
            sA[r * 61 + cc] = pointwise(__ldg(base + r * WSZ + cc));
        }
    } else {
        for (int i = tid; i < 60 * 60; i += 256) {
            int r = i / 60, cc = i - r * 60;
            int gy = ty0 - 14 + r, gx = tx0 - 14 + cc;
            float v = 0.f;
            if ((unsigned)gy < HSZ && (unsigned)gx < WSZ)
                v = pointwise(__ldg(xin + gy * WSZ + gx));
            sA[r * 61 + cc] = v;
        }
    }
    __syncthreads();

    // ---- H1: sA -> sB. 30 row-pairs x 8 segs x 6 outputs. window 20 pairs ----
    {
        int rp = tid >> 3, seg = tid & 7;
        if (rp < 30) {
            int c0 = seg * 6;
            const float* a0 = &sA[(2 * rp) * 61 + c0];
            const float* a1 = a0 + 61;
            ull w[20];
            #pragma unroll
            for (int i = 0; i < 20; ++i) w[i] = pack2(a0[i], a1[i]);  // col overrun feeds only discarded outputs
            ull acc[6] = {};
            #pragma unroll
            for (int k = 0; k < 15; ++k) {
                ull wk = sW[k];
                #pragma unroll
                for (int j = 0; j < 6; ++j) acc[j] = fma2(w[j + k], wk, acc[j]);
            }
            float* b0 = &sB[(2 * rp) * 48 + c0];
            #pragma unroll
            for (int j = 0; j < 6; ++j) {
                if (c0 + j < 46) {
                    float lo, hi; unpack2(acc[j], lo, hi);
                    b0[j] = lo; b0[48 + j] = hi;
                }
            }
        }
    }
    __syncthreads();

    // ---- V1 + LCE epilogue: sB -> sC. 23 col-pairs x 8 strips x 6 rows ----
    if (tid < 184) {
        int cp = tid % 23, strip = tid / 23;
        int r0 = strip * 6;
        const ull* bp = (const ull*)&sB[r0 * 48 + 2 * cp];    // stride 24 ull; rows 60/61 junk -> discarded accs
        ull w[20];
        #pragma unroll
        for (int i = 0; i < 20; ++i) w[i] = bp[i * 24];
        ull acc[6] = {};
        #pragma unroll
        for (int k = 0; k < 15; ++k) {
            ull wk = sW[k];
            #pragma unroll
            for (int j = 0; j < 6; ++j) acc[j] = fma2(w[j + k], wk, acc[j]);
        }
        #pragma unroll
        for (int j = 0; j < 6; ++j) {
            int rr = r0 + j;
            if (rr < 46) {
                float m0, m1; unpack2(acc[j], m0, m1);
                int gy = ty0 - 7 + rr, gx = tx0 - 7 + 2 * cp;
                float a0c = sA[(rr + 7) * 61 + 2 * cp + 7];
                float a1c = sA[(rr + 7) * 61 + 2 * cp + 8];
                float v0 = ((unsigned)gy < HSZ && (unsigned)gx < WSZ)
                           ? fmaf(eav, a0c - m0, a0c) : 0.f;   // x + ea*(x - mean); 0 outside image
                float v1 = ((unsigned)gy < HSZ && (unsigned)(gx + 1) < WSZ)
                           ? fmaf(eav, a1c - m1, a1c) : 0.f;
                *(float2*)&sC[rr * 48 + 2 * cp] = make_float2(v0, v1);
            }
        }
    }
    __syncthreads();

    // ---- H2: sC -> sD. 23 row-pairs x 8 segs x 4 outputs. window 18 pairs ----
    {
        int rp = tid >> 3, seg = tid & 7;
        if (rp < 23) {
            int c0 = seg * 4;
            const float* p0 = &sC[(2 * rp) * 48 + c0];
            const float* p1 = p0 + 48;
            ull w[18];
            #pragma unroll
            for (int i = 0; i < 18; ++i) w[i] = pack2(p0[i], p1[i]);
            ull acc[4] = {};
            #pragma unroll
            for (int k = 0; k < 15; ++k) {
                ull wk = sW[k];
                #pragma unroll
                for (int j = 0; j < 4; ++j) acc[j] = fma2(w[j + k], wk, acc[j]);
            }
            float* d0 = &sD[(2 * rp) * 34 + c0];
            #pragma unroll
            for (int j = 0; j < 4; ++j) {
                float lo, hi; unpack2(acc[j], lo, hi);
                d0[j] = lo; d0[34 + j] = hi;
            }
        }
    }
    __syncthreads();

    // ---- V2 + softness + gradient mask -> out. 16 col-pairs x 8 strips x 4 rows ----
    if (tid < 128) {
        int cp = tid & 15, strip = tid >> 4;
        int r0 = strip * 4;
        const ull* dp = (const ull*)&sD[r0 * 34 + 2 * cp];    // stride 17 ull
        ull w[18];
        #pragma unroll
        for (int i = 0; i < 18; ++i) w[i] = dp[i * 17];
        ull acc[4] = {};
        #pragma unroll
        for (int k = 0; k < 15; ++k) {
            ull wk = sW[k];
            #pragma unroll
            for (int j = 0; j < 4; ++j) acc[j] = fma2(w[j + k], wk, acc[j]);
        }
        float* __restrict__ op = out + (size_t)img * (HSZ * WSZ);
        const float yscale = 2.f / (float)(HSZ - 1);
        const float xscale = 2.f / (float)(WSZ - 1);
        #pragma unroll
        for (int j = 0; j < 4; ++j) {
            int r  = r0 + j;
            int gy = ty0 + r, gx = tx0 + 2 * cp;
            float b0, b1; unpack2(acc[j], b0, b1);
            float x50 = sC[(r + 7) * 48 + 2 * cp + 7];
            float x51 = sC[(r + 7) * 48 + 2 * cp + 8];
            float v0 = sof * b0 + (1.f - sof) * x50;           // softness blend
            float v1 = sof * b1 + (1.f - sof) * x51;
            float yn  = fmaf((float)gy, yscale, -1.f);
            float xn0 = fmaf((float)gx, xscale, -1.f);
            float xn1 = fmaf((float)(gx + 1), xscale, -1.f);
            float gr0 = xn0 * cst + yn * snt;
            float gr1 = xn1 * cst + yn * snt;
            float mk0 = 1.f / (1.f + __expf(hrd * gr0));       // sigmoid(-hardness*gr)
            float mk1 = 1.f / (1.f + __expf(hrd * gr1));
            v0 = fminf(fmaxf(v0 * (1.f - itn * mk0), 0.f), 1.f);
            v1 = fminf(fmaxf(v1 * (1.f - itn * mk1), 0.f), 1.f);
            *(float2*)&op[gy * WSZ + gx] = make_float2(v0, v1);
        }
    }
}

extern "C" void kernel_launch(void* const* d_in, const int* in_sizes, int n_in,
                              void* d_out, int out_size) {
    (void)in_sizes; (void)n_in; (void)out_size;
    dim3 grid(WSZ / TILE, HSZ / TILE, NIMG);   // 32 x 32 x 12 = 12288 CTAs
    proc_kernel<<<grid, 256>>>(
        (const float*)d_in[0],  // x
        (const float*)d_in[1],  // gains
        (const float*)d_in[2],  // gamma
        (const float*)d_in[3],  // shadow_boost
        (const float*)d_in[4],  // highlight_reduce
        (const float*)d_in[5],  // brightness
        (const float*)d_in[6],  // contrast
        (const float*)d_in[7],  // enhance_amount
        (const float*)d_in[8],  // softness
        (const float*)d_in[9],  // intensity
        (const float*)d_in[10], // rotation
        (const float*)d_in[11], // hardness
        (float*)d_out);
}

// round 8
// speedup vs baseline: 2.2126x; 2.2126x over previous
#include <cuda_runtime.h>
#include <math.h>

#define HSZ 1024
#define WSZ 1024
#define NIMG 12            // B*C = 4*3
#define TILE 64            // output tile (64x64), 512 threads
#define NPIX (NIMG * HSZ * WSZ)

// ---------------------------------------------------------------------------
// Scratch: pointwise-processed image x4 (stage after brightness/contrast).
// __device__ global array = allowed scratch (no allocation).
// ---------------------------------------------------------------------------
__device__ float g_x4[NPIX];

// ---------------------------------------------------------------------------
// Compile-time Gaussian weights (KSIZE=15, SIGMA=3) via constexpr exp-series.
// Literals -> FFMA-imm form (rt_SMSP=1).
// ---------------------------------------------------------------------------
__host__ __device__ constexpr double cexp_(double x) {
    double t = 1.0, s = 1.0;
    for (int i = 1; i < 60; ++i) { t *= x / i; s += t; }
    return s;
}
__host__ __device__ constexpr double gsum_() {
    double s = 0.0;
    for (int i = 0; i < 15; ++i) { double d = i - 7; s += cexp_(-d * d / 18.0); }
    return s;
}
__host__ __device__ constexpr float gw_(int k) {
    double d = k - 7; return (float)(cexp_(-d * d / 18.0) / gsum_());
}
#define GWDECL constexpr float GW[15] = {gw_(0), gw_(1), gw_(2),  gw_(3),  gw_(4),  \
    gw_(5),  gw_(6), gw_(7), gw_(8), gw_(9), gw_(10), gw_(11), gw_(12), gw_(13), gw_(14)}

__device__ __forceinline__ float tanh_approx(float x) {
    float y; asm("tanh.approx.f32 %0, %1;" : "=f"(y) : "f"(x));
    return y;
}

// ---------------------------------------------------------------------------
// K1: pointwise chain, 1x per pixel, float4. x4 = bc(sh(gamma(wb(x))))
//   sigmoid(t) = 0.5*(1+tanh(t/2)) -> one tanh.approx per pixel
// ---------------------------------------------------------------------------
__global__ __launch_bounds__(256) void pointwise_kernel(
    const float* __restrict__ x, const float* __restrict__ gains,
    const float* __restrict__ p_gamma, const float* __restrict__ p_sb,
    const float* __restrict__ p_hr, const float* __restrict__ p_br,
    const float* __restrict__ p_ct)
{
    const int idx4 = blockIdx.x * 256 + threadIdx.x;          // one float4 per thread
    const int ch   = (idx4 >> 18) % 3;                        // 262144 float4 per channel plane
    const float gain = gains[ch];
    const float gam  = p_gamma[0];
    const float sbv  = p_sb[0], hrv = p_hr[0];
    const float shc  = -(sbv + hrv);                          // v + sbv - (sbv+hrv)*hi
    const float brv  = p_br[0], ctv = p_ct[0];
    const float bc0  = 0.5f + brv;

    float4 v4 = __ldg((const float4*)x + idx4);
    float* v = &v4.x;
    #pragma unroll
    for (int i = 0; i < 4; ++i) {
        float t = __powf(v[i] * gain, gam);                   // WB + gamma
        float hi = fmaf(tanh_approx((t - 0.5f) * 5.f), 0.5f, 0.5f);
        t = fmaf(shc, hi, t + sbv);                           // shadow/highlight
        t = fminf(fmaxf(t, 0.f), 1.f);
        t = fmaf(ctv, t - 0.5f, bc0);                         // brightness/contrast
        v[i] = fminf(fmaxf(t, 0.f), 1.f);
    }
    ((float4*)g_x4)[idx4] = v4;
}

// ---------------------------------------------------------------------------
// K2: blur cascade per 64x64 tile (512 threads, dynamic smem 88,992 B):
//   phase0: 92x92 halo copy from g_x4 -> sA (stride 94)
//   H1: sA -> sB [92 x 78]  (stride 80)      460 thr: 92 rows x 5 segs x 16 cols
//   V1+LCE: sB -> sC [78 x 78] (stride 80)   468 thr: 78 cols x 6 strips x 13 rows
//   H2: sC -> sD [78 x 64] (stride 66, aliases sA)  468 thr: 78 rows x 6 segs x 11
//   V2+softness+mask -> out                  512 thr: 64 cols x 8 strips x 8 rows
// Scatter form: stream one input value into NOUT static accumulators; window
// overrun only ever feeds accumulators that are discarded by static guards.
// ---------------------------------------------------------------------------
__global__ __launch_bounds__(512, 2) void blur_kernel(
    const float* __restrict__ p_ea, const float* __restrict__ p_soft,
    const float* __restrict__ p_int, const float* __restrict__ p_rot,
    const float* __restrict__ p_hard, float* __restrict__ out)
{
    GWDECL;
    extern __shared__ float smem[];
    float* const sA = smem;                 // 92*94 = 8648
    float* const sB = smem + 8648;          // 92*80 = 7360
    float* const sC = smem + 8648 + 7360;   // 78*80 = 6240
    float* const sD = sA;                   // 78*66 = 5148 (alias; sA dead after V1)

    const int tid = threadIdx.x;
    const int img = blockIdx.z;
    const int ty0 = blockIdx.y * TILE;
    const int tx0 = blockIdx.x * TILE;

    const float eav = p_ea[0], sof = p_soft[0];
    const float itn = p_int[0], hrd = p_hard[0];
    float snt, cst;
    sincosf(p_rot[0] * 0.017453292519943295f, &snt, &cst);

    const float* __restrict__ xin = g_x4 + (size_t)img * (HSZ * WSZ);
    const bool interior = (ty0 >= 14) && (ty0 + 78 <= HSZ) && (tx0 >= 14) && (tx0 + 78 <= WSZ);

    // ---- phase 0: halo copy (zero-pad outside image) ----
    if (interior) {
        const float* __restrict__ base = xin + (ty0 - 14) * WSZ + (tx0 - 14);  // even col -> 8B aligned
        for (int p = tid; p < 92 * 46; p += 512) {
            int r = p / 46, m = p - r * 46;
            float2 v = __ldg((const float2*)(base + r * WSZ) + m);
            sA[r * 94 + 2 * m]     = v.x;
            sA[r * 94 + 2 * m + 1] = v.y;
        }
    } else {
        for (int p = tid; p < 92 * 92; p += 512) {
            int r = p / 92, c = p - r * 92;
            int gy = ty0 - 14 + r, gx = tx0 - 14 + c;
            float v = 0.f;
            if ((unsigned)gy < HSZ && (unsigned)gx < WSZ) v = __ldg(xin + gy * WSZ + gx);
            sA[r * 94 + c] = v;
        }
    }
    __syncthreads();

    // ---- H1: 92 rows x 78 cols. 16 outputs/thread, window 30 ----
    if (tid < 460) {
        int r = tid / 5, seg = tid - 5 * r;
        int c0 = seg * 16;
        const float* a = &sA[r * 94 + c0];
        float acc[16] = {};
        #pragma unroll
        for (int i = 0; i < 30; ++i) {
            float v = a[i];                         // cols 92,93 junk -> only discarded accs
            #pragma unroll
            for (int k = 0; k < 15; ++k) {
                int j = i - k;
                if (j >= 0 && j < 16) acc[j] = fmaf(v, GW[k], acc[j]);
            }
        }
        float* b = &sB[r * 80 + c0];
        #pragma unroll
        for (int j = 0; j < 16; ++j)
            if (c0 + j < 78) b[j] = acc[j];
    }
    __syncthreads();

    // ---- V1 + LCE epilogue: 78 cols x 78 rows. 13 rows/thread, window 27 ----
    if (tid < 468) {
        int strip = tid / 78, ccol = tid - 78 * strip;
        int r0 = strip * 13;
        const float* b = &sB[r0 * 80 + ccol];
        float acc[13] = {};
        #pragma unroll
        for (int i = 0; i < 27; ++i) {              // rows r0..r0+26 <= 91, all real
            float v = b[i * 80];
            #pragma unroll
            for (int k = 0; k < 15; ++k) {
                int j = i - k;
                if (j >= 0 && j < 13) acc[j] = fmaf(v, GW[k], acc[j]);
            }
        }
        if (interior) {
            #pragma unroll
            for (int j = 0; j < 13; ++j) {
                int rr = r0 + j;
                float a = sA[(rr + 7) * 94 + ccol + 7];
                sC[rr * 80 + ccol] = fmaf(eav, a - acc[j], a);   // x + ea*(x - mean)
            }
        } else {
            #pragma unroll
            for (int j = 0; j < 13; ++j) {
                int rr = r0 + j;
                int gy = ty0 - 7 + rr, gx = tx0 - 7 + ccol;
                float val = 0.f;
                if ((unsigned)gy < HSZ && (unsigned)gx < WSZ) {
                    float a = sA[(rr + 7) * 94 + ccol + 7];
                    val = fmaf(eav, a - acc[j], a);
                }
                sC[rr * 80 + ccol] = val;           // zero outside image = blur2 zero-pad
            }
        }
    }
    __syncthreads();

    // ---- H2: 78 rows x 64 cols. 11 outputs/thread, window 25 ----
    if (tid < 468) {
        int r = tid / 6, seg = tid - 6 * r;
        int c0 = seg * 11;
        const float* c = &sC[r * 80 + c0];
        float acc[11] = {};
        #pragma unroll
        for (int i = 0; i < 25; ++i) {
            float v = c[i];                         // cols 78,79 junk -> only discarded accs
            #pragma unroll
            for (int k = 0; k < 15; ++k) {
                int j = i - k;
                if (j >= 0 && j < 11) acc[j] = fmaf(v, GW[k], acc[j]);
            }
        }
        float* d = &sD[r * 66 + c0];
        #pragma unroll
        for (int j = 0; j < 11; ++j)
            if (c0 + j < 64) d[j] = acc[j];
    }
    __syncthreads();

    // ---- V2 + softness + gradient mask -> out. 64 cols x 8 strips x 8 rows ----
    {
        int strip = tid >> 6, cc = tid & 63;
        int r0 = strip * 8;
        const float* d = &sD[r0 * 66 + cc];
        float acc[8] = {};
        #pragma unroll
        for (int i = 0; i < 22; ++i) {              // rows r0..r0+21 <= 77, all real
            float v = d[i * 66];
            #pragma unroll
            for (int k = 0; k < 15; ++k) {
                int j = i - k;
                if (j >= 0 && j < 8) acc[j] = fmaf(v, GW[k], acc[j]);
            }
        }
        float* __restrict__ op = out + (size_t)img * (HSZ * WSZ);
        const float yscale = 2.f / (float)(HSZ - 1);
        const float xscale = 2.f / (float)(WSZ - 1);
        const float mc = 1.f - 0.5f * itn;          // factor = mc + md*tanh(-hrd*gr/2)
        const float md = -0.5f * itn;
        const int gx = tx0 + cc;
        const float xn = fmaf((float)gx, xscale, -1.f);
        #pragma unroll
        for (int j = 0; j < 8; ++j) {
            int gy = ty0 + r0 + j;
            float x5c = sC[(r0 + j + 7) * 80 + cc + 7];
            float v = sof * acc[j] + (1.f - sof) * x5c;        // softness blend
            float yn = fmaf((float)gy, yscale, -1.f);
            float gr = xn * cst + yn * snt;
            float fac = fmaf(md, tanh_approx(-0.5f * hrd * gr), mc);  // 1 - itn*sigmoid(-hrd*gr)
            v = fminf(fmaxf(v * fac, 0.f), 1.f);
            op[gy * WSZ + gx] = v;
        }
    }
}

extern "C" void kernel_launch(void* const* d_in, const int* in_sizes, int n_in,
                              void* d_out, int out_size) {
    (void)in_sizes; (void)n_in; (void)out_size;

    static const int SMEM_BYTES = (8648 + 7360 + 6240) * 4;   // 88,992
    cudaFuncSetAttribute(blur_kernel, cudaFuncAttributeMaxDynamicSharedMemorySize, SMEM_BYTES);

    pointwise_kernel<<<NPIX / 4 / 256, 256>>>(
        (const float*)d_in[0],  // x
        (const float*)d_in[1],  // gains
        (const float*)d_in[2],  // gamma
        (const float*)d_in[3],  // shadow_boost
        (const float*)d_in[4],  // highlight_reduce
        (const float*)d_in[5],  // brightness
        (const float*)d_in[6]); // contrast

    dim3 grid(WSZ / TILE, HSZ / TILE, NIMG);                  // 16 x 16 x 12 = 3072 CTAs
    blur_kernel<<<grid, 512, SMEM_BYTES>>>(
        (const float*)d_in[7],  // enhance_amount
        (const float*)d_in[8],  // softness
        (const float*)d_in[9],  // intensity
        (const float*)d_in[10], // rotation
        (const float*)d_in[11], // hardness
        (float*)d_out);
}

// round 9
// speedup vs baseline: 2.4435x; 1.1043x over previous
#include <cuda_runtime.h>
#include <math.h>

#define HSZ 1024
#define WSZ 1024
#define NIMG 12            // B*C = 4*3
#define TILE 64            // output tile (64x64), 512 threads
#define NPIX (NIMG * HSZ * WSZ)

// ---------------------------------------------------------------------------
// Scratch: pointwise-processed image x4 (stage after brightness/contrast).
// ---------------------------------------------------------------------------
__device__ float g_x4[NPIX];

// ---------------------------------------------------------------------------
// Compile-time Gaussian weights (KSIZE=15, SIGMA=3) via constexpr exp-series.
// Literals -> FFMA-imm form (rt_SMSP=1).
// ---------------------------------------------------------------------------
__host__ __device__ constexpr double cexp_(double x) {
    double t = 1.0, s = 1.0;
    for (int i = 1; i < 60; ++i) { t *= x / i; s += t; }
    return s;
}
__host__ __device__ constexpr double gsum_() {
    double s = 0.0;
    for (int i = 0; i < 15; ++i) { double d = i - 7; s += cexp_(-d * d / 18.0); }
    return s;
}
__host__ __device__ constexpr float gw_(int k) {
    double d = k - 7; return (float)(cexp_(-d * d / 18.0) / gsum_());
}
#define GWDECL constexpr float GW[15] = {gw_(0), gw_(1), gw_(2),  gw_(3),  gw_(4),  \
    gw_(5),  gw_(6), gw_(7), gw_(8), gw_(9), gw_(10), gw_(11), gw_(12), gw_(13), gw_(14)}

__device__ __forceinline__ float tanh_approx(float x) {
    float y; asm("tanh.approx.f32 %0, %1;" : "=f"(y) : "f"(x));
    return y;
}

// ---------------------------------------------------------------------------
// K1: pointwise chain, 1x per pixel, float4.
// ---------------------------------------------------------------------------
__global__ __launch_bounds__(256) void pointwise_kernel(
    const float* __restrict__ x, const float* __restrict__ gains,
    const float* __restrict__ p_gamma, const float* __restrict__ p_sb,
    const float* __restrict__ p_hr, const float* __restrict__ p_br,
    const float* __restrict__ p_ct)
{
    const int idx4 = blockIdx.x * 256 + threadIdx.x;
    const int ch   = (idx4 >> 18) % 3;
    const float gain = gains[ch];
    const float gam  = p_gamma[0];
    const float sbv  = p_sb[0], hrv = p_hr[0];
    const float shc  = -(sbv + hrv);
    const float brv  = p_br[0], ctv = p_ct[0];
    const float bc0  = 0.5f + brv;

    float4 v4 = __ldg((const float4*)x + idx4);
    float* v = &v4.x;
    #pragma unroll
    for (int i = 0; i < 4; ++i) {
        float t = __powf(v[i] * gain, gam);                   // WB + gamma
        float hi = fmaf(tanh_approx((t - 0.5f) * 5.f), 0.5f, 0.5f);
        t = fmaf(shc, hi, t + sbv);                           // shadow/highlight
        t = fminf(fmaxf(t, 0.f), 1.f);
        t = fmaf(ctv, t - 0.5f, bc0);                         // brightness/contrast
        v[i] = fminf(fmaxf(t, 0.f), 1.f);
    }
    ((float4*)g_x4)[idx4] = v4;
}

// ---------------------------------------------------------------------------
// K2: blur cascade per 64x64 tile (512 threads, dynamic smem 90,040 B).
// Bank-conflict-free layout:
//   sA stride 95 (95%32=31), sB/sC stride 81 (81%32=17), sD stride 67 (67%32=3)
//   H-passes use ROW-FAST lane mapping (r = tid % NROWS) so lane address
//   stride = row stride (coprime with 32) -> all 32 banks.
//   V-passes use consecutive-lane columns (always conflict-free).
// Phases:
//   phase0: 92x92 halo copy from g_x4 -> sA
//   H1: sA -> sB [92 x 78]       460 thr: r=tid%92, seg=tid/92 (5 segs x 16)
//   V1+LCE: sB -> sC [78 x 78]   468 thr: ccol=tid%78, strip=tid/78 (6 x 13)
//   H2: sC -> sD [78 x 64]       468 thr: r=tid%78, seg=tid/78 (6 segs x 11)
//   V2+softness+mask -> out      512 thr: cc=tid&63, strip=tid>>6 (8 x 8)
// ---------------------------------------------------------------------------
__global__ __launch_bounds__(512, 2) void blur_kernel(
    const float* __restrict__ p_ea, const float* __restrict__ p_soft,
    const float* __restrict__ p_int, const float* __restrict__ p_rot,
    const float* __restrict__ p_hard, float* __restrict__ out)
{
    GWDECL;
    extern __shared__ float smem[];
    float* const sA = smem;                 // 92*95 = 8740
    float* const sB = smem + 8740;          // 92*81 = 7452
    float* const sC = smem + 8740 + 7452;   // 78*81 = 6318
    float* const sD = sA;                   // 78*67 = 5226 (alias; sA dead after V1)

    const int tid = threadIdx.x;
    const int img = blockIdx.z;
    const int ty0 = blockIdx.y * TILE;
    const int tx0 = blockIdx.x * TILE;

    const float eav = p_ea[0], sof = p_soft[0];
    const float itn = p_int[0], hrd = p_hard[0];
    float snt, cst;
    sincosf(p_rot[0] * 0.017453292519943295f, &snt, &cst);

    const float* __restrict__ xin = g_x4 + (size_t)img * (HSZ * WSZ);
    const bool interior = (ty0 >= 14) && (ty0 + 78 <= HSZ) && (tx0 >= 14) && (tx0 + 78 <= WSZ);

    // ---- phase 0: halo copy (zero-pad outside image) ----
    if (interior) {
        const float* __restrict__ base = xin + (ty0 - 14) * WSZ + (tx0 - 14);  // even col -> 8B aligned
        for (int p = tid; p < 92 * 46; p += 512) {
            int r = p / 46, m = p - r * 46;
            float2 v = __ldg((const float2*)(base + r * WSZ) + m);
            sA[r * 95 + 2 * m]     = v.x;
            sA[r * 95 + 2 * m + 1] = v.y;
        }
    } else {
        for (int p = tid; p < 92 * 92; p += 512) {
            int r = p / 92, c = p - r * 92;
            int gy = ty0 - 14 + r, gx = tx0 - 14 + c;
            float v = 0.f;
            if ((unsigned)gy < HSZ && (unsigned)gx < WSZ) v = __ldg(xin + gy * WSZ + gx);
            sA[r * 95 + c] = v;
        }
    }
    __syncthreads();

    // ---- H1: 92 rows x 78 cols. row-fast lanes, 16 outputs/thread, window 30 ----
    if (tid < 460) {
        int r = tid % 92, seg = tid / 92;
        int c0 = seg * 16;
        const float* a = &sA[r * 95 + c0];
        float acc[16] = {};
        #pragma unroll
        for (int i = 0; i < 30; ++i) {
            float v = a[i];                         // cols >=92 junk -> only discarded accs
            #pragma unroll
            for (int k = 0; k < 15; ++k) {
                int j = i - k;
                if (j >= 0 && j < 16) acc[j] = fmaf(v, GW[k], acc[j]);
            }
        }
        float* b = &sB[r * 81 + c0];
        #pragma unroll
        for (int j = 0; j < 16; ++j)
            if (c0 + j < 78) b[j] = acc[j];
    }
    __syncthreads();

    // ---- V1 + LCE epilogue: 78 cols x 78 rows. 13 rows/thread, window 27 ----
    if (tid < 468) {
        int strip = tid / 78, ccol = tid - 78 * strip;
        int r0 = strip * 13;
        const float* b = &sB[r0 * 81 + ccol];
        float acc[13] = {};
        #pragma unroll
        for (int i = 0; i < 27; ++i) {              // rows r0..r0+26 <= 91, all real
            float v = b[i * 81];
            #pragma unroll
            for (int k = 0; k < 15; ++k) {
                int j = i - k;
                if (j >= 0 && j < 13) acc[j] = fmaf(v, GW[k], acc[j]);
            }
        }
        if (interior) {
            #pragma unroll
            for (int j = 0; j < 13; ++j) {
                int rr = r0 + j;
                float a = sA[(rr + 7) * 95 + ccol + 7];
                sC[rr * 81 + ccol] = fmaf(eav, a - acc[j], a);   // x + ea*(x - mean)
            }
        } else {
            #pragma unroll
            for (int j = 0; j < 13; ++j) {
                int rr = r0 + j;
                int gy = ty0 - 7 + rr, gx = tx0 - 7 + ccol;
                float val = 0.f;
                if ((unsigned)gy < HSZ && (unsigned)gx < WSZ) {
                    float a = sA[(rr + 7) * 95 + ccol + 7];
                    val = fmaf(eav, a - acc[j], a);
                }
                sC[rr * 81 + ccol] = val;           // zero outside image = blur2 zero-pad
            }
        }
    }
    __syncthreads();

    // ---- H2: 78 rows x 64 cols. row-fast lanes, 11 outputs/thread, window 25 ----
    if (tid < 468) {
        int r = tid % 78, seg = tid / 78;
        int c0 = seg * 11;
        const float* c = &sC[r * 81 + c0];
        float acc[11] = {};
        #pragma unroll
        for (int i = 0; i < 25; ++i) {
            float v = c[i];                         // cols 78..79 junk -> only discarded accs
            #pragma unroll
            for (int k = 0; k < 15; ++k) {
                int j = i - k;
                if (j >= 0 && j < 11) acc[j] = fmaf(v, GW[k], acc[j]);
            }
        }
        float* d = &sD[r * 67 + c0];
        #pragma unroll
        for (int j = 0; j < 11; ++j)
            if (c0 + j < 64) d[j] = acc[j];
    }
    __syncthreads();

    // ---- V2 + softness + gradient mask -> out. 64 cols x 8 strips x 8 rows ----
    {
        int strip = tid >> 6, cc = tid & 63;
        int r0 = strip * 8;
        const float* d = &sD[r0 * 67 + cc];
        float acc[8] = {};
        #pragma unroll
        for (int i = 0; i < 22; ++i) {              // rows r0..r0+21 <= 77, all real
            float v = d[i * 67];
            #pragma unroll
            for (int k = 0; k < 15; ++k) {
                int j = i - k;
                if (j >= 0 && j < 8) acc[j] = fmaf(v, GW[k], acc[j]);
            }
        }
        float* __restrict__ op = out + (size_t)img * (HSZ * WSZ);
        const float yscale = 2.f / (float)(HSZ - 1);
        const float xscale = 2.f / (float)(WSZ - 1);
        const float mc = 1.f - 0.5f * itn;          // factor = mc + md*tanh(-hrd*gr/2)
        const float md = -0.5f * itn;
        const int gx = tx0 + cc;
        const float xn = fmaf((float)gx, xscale, -1.f);
        #pragma unroll
        for (int j = 0; j < 8; ++j) {
            int gy = ty0 + r0 + j;
            float x5c = sC[(r0 + j + 7) * 81 + cc + 7];
            float v = sof * acc[j] + (1.f - sof) * x5c;        // softness blend
            float yn = fmaf((float)gy, yscale, -1.f);
            float gr = xn * cst + yn * snt;
            float fac = fmaf(md, tanh_approx(-0.5f * hrd * gr), mc);  // 1 - itn*sigmoid(-hrd*gr)
            v = fminf(fmaxf(v * fac, 0.f), 1.f);
            op[gy * WSZ + gx] = v;
        }
    }
}

extern "C" void kernel_launch(void* const* d_in, const int* in_sizes, int n_in,
                              void* d_out, int out_size) {
    (void)in_sizes; (void)n_in; (void)out_size;

    static const int SMEM_BYTES = (8740 + 7452 + 6318) * 4;   // 90,040
    cudaFuncSetAttribute(blur_kernel, cudaFuncAttributeMaxDynamicSharedMemorySize, SMEM_BYTES);

    pointwise_kernel<<<NPIX / 4 / 256, 256>>>(
        (const float*)d_in[0],  // x
        (const float*)d_in[1],  // gains
        (const float*)d_in[2],  // gamma
        (const float*)d_in[3],  // shadow_boost
        (const float*)d_in[4],  // highlight_reduce
        (const float*)d_in[5],  // brightness
        (const float*)d_in[6]); // contrast

    dim3 grid(WSZ / TILE, HSZ / TILE, NIMG);                  // 16 x 16 x 12 = 3072 CTAs
    blur_kernel<<<grid, 512, SMEM_BYTES>>>(
        (const float*)d_in[7],  // enhance_amount
        (const float*)d_in[8],  // softness
        (const float*)d_in[9],  // intensity
        (const float*)d_in[10], // rotation
        (const float*)d_in[11], // hardness
        (float*)d_out);
}